// round 3
// baseline (speedup 1.0000x reference)
#include <cuda_runtime.h>
#include <math.h>

// Problem constants
#define BB 64      // batch
#define TT 256     // time steps
#define DD 1024    // input dim
#define HH 1024    // hidden dim
#define LL 4       // layers
#define GG 4096    // 4*H gate width
#define NBLK 128   // persistent grid size (1 block/SM, co-resident)

typedef unsigned long long ull;

// ---------------------------------------------------------------------------
// Scratch (static device globals; no runtime allocation allowed)
// ---------------------------------------------------------------------------
__device__ float g_gx[(size_t)TT * BB * GG];    // [T*B, 4H] input-side gate pre-activations
__device__ float g_hseq[(size_t)TT * BB * HH];  // [T, B, H] layer output sequence
__device__ float g_hbuf[2][BB][HH];             // double-buffered hidden state
__device__ unsigned g_bar_count;                // grid barrier state (zero-init)
__device__ volatile unsigned g_bar_gen;

// ---------------------------------------------------------------------------
// Packed fp32x2 helpers
// ---------------------------------------------------------------------------
__device__ __forceinline__ void ffma2(ull& d, ull a, ull b) {
    asm("fma.rn.f32x2 %0,%1,%2,%0;" : "+l"(d) : "l"(a), "l"(b));
}
__device__ __forceinline__ float2 unpack2(ull v) {
    float2 f; asm("mov.b64 {%0,%1},%2;" : "=f"(f.x), "=f"(f.y) : "l"(v)); return f;
}

// ---------------------------------------------------------------------------
// Software grid barrier (all NBLK blocks co-resident)
// ---------------------------------------------------------------------------
__device__ __forceinline__ void grid_sync() {
    __syncthreads();
    if (threadIdx.x == 0) {
        __threadfence();
        unsigned gen = g_bar_gen;
        if (atomicAdd(&g_bar_count, 1u) == NBLK - 1) {
            g_bar_count = 0;
            __threadfence();
            g_bar_gen = gen + 1;
        } else {
            while (g_bar_gen == gen) { }
            __threadfence();
        }
    }
    __syncthreads();
}

// ---------------------------------------------------------------------------
// Big input GEMM: g_gx[m][n] = sum_k A[m][k]*W[k][n] + bias[n]
// 128x128 tile, BK=8, 256 threads, 8x8 micro-tile.
// A staged REPLICATED (pairs (v,v)) so FFMA2 operands need no packing movs.
// Double-buffered, one bar.sync per chunk.
// ---------------------------------------------------------------------------
#define APAD 260   // 256 + 4 (replicated row length, 16B-aligned, bank-skewed)

__global__ __launch_bounds__(256) void gemm_in_kernel(
    const float* __restrict__ xin, long sT, long sB,
    const float* __restrict__ W, const float* __restrict__ bias,
    int use_hseq)
{
    __shared__ float Asr[2][8][APAD];   // replicated: Asr[k][2r]=Asr[k][2r+1]=a[r]
    __shared__ float Ws[2][8][128];

    const float* A = use_hseq ? (const float*)g_hseq : xin;

    int tid = threadIdx.x;

    // A loader: 128 rows x 8 k
    int aRow = tid >> 1;
    int aK   = (tid & 1) * 4;
    int m    = blockIdx.y * 128 + aRow;
    const float* Arow = A + (size_t)(m & (BB - 1)) * sB + (size_t)(m >> 6) * sT;

    // W loader: 8 k x 128 cols
    int wK   = tid >> 5;
    int wCol = (tid & 31) * 4;
    const float* Wp = W + (size_t)wK * GG + blockIdx.x * 128 + wCol;

    int trow = tid >> 4;   // 0..15 -> rows trow*8..+7
    int tcol = tid & 15;   // 0..15 -> cols tcol*8..+7

    ull acc[8][4];
#pragma unroll
    for (int i = 0; i < 8; i++)
#pragma unroll
        for (int j = 0; j < 4; j++) acc[i][j] = 0ull;

    // prologue loads
    float4 av = *(const float4*)(Arow + aK);
    float4 wv = *(const float4*)(Wp);

    for (int c = 0; c < 128; ++c) {
        int b = c & 1;
        // stage current chunk (replicated A)
        Asr[b][aK + 0][2 * aRow]     = av.x; Asr[b][aK + 0][2 * aRow + 1] = av.x;
        Asr[b][aK + 1][2 * aRow]     = av.y; Asr[b][aK + 1][2 * aRow + 1] = av.y;
        Asr[b][aK + 2][2 * aRow]     = av.z; Asr[b][aK + 2][2 * aRow + 1] = av.z;
        Asr[b][aK + 3][2 * aRow]     = av.w; Asr[b][aK + 3][2 * aRow + 1] = av.w;
        *(float4*)&Ws[b][wK][wCol] = wv;
        __syncthreads();

        if (c < 127) {
            long k0 = (long)(c + 1) * 8;
            av = *(const float4*)(Arow + k0 + aK);
            wv = *(const float4*)(Wp + k0 * GG);
        }

#pragma unroll
        for (int k = 0; k < 8; ++k) {
            // 8 replicated row-pairs via 4x LDS.128
            ulonglong2 a01 = *(const ulonglong2*)&Asr[b][k][trow * 16];
            ulonglong2 a23 = *(const ulonglong2*)&Asr[b][k][trow * 16 + 4];
            ulonglong2 a45 = *(const ulonglong2*)&Asr[b][k][trow * 16 + 8];
            ulonglong2 a67 = *(const ulonglong2*)&Asr[b][k][trow * 16 + 12];
            // 4 natural col-pairs via 2x LDS.128
            ulonglong2 w01 = *(const ulonglong2*)&Ws[b][k][tcol * 8];
            ulonglong2 w23 = *(const ulonglong2*)&Ws[b][k][tcol * 8 + 4];
            ull ar[8] = {a01.x, a01.y, a23.x, a23.y, a45.x, a45.y, a67.x, a67.y};
#pragma unroll
            for (int i = 0; i < 8; i++) {
                ffma2(acc[i][0], ar[i], w01.x);
                ffma2(acc[i][1], ar[i], w01.y);
                ffma2(acc[i][2], ar[i], w23.x);
                ffma2(acc[i][3], ar[i], w23.y);
            }
        }
        __syncthreads();
    }

    int rowBase = blockIdx.y * 128 + trow * 8;
    int colBase = blockIdx.x * 128 + tcol * 8;
    float4 b0 = *(const float4*)&bias[colBase];
    float4 b1 = *(const float4*)&bias[colBase + 4];
    float bb[8] = {b0.x, b0.y, b0.z, b0.w, b1.x, b1.y, b1.z, b1.w};

#pragma unroll
    for (int i = 0; i < 8; i++) {
        size_t off = (size_t)(rowBase + i) * GG + colBase;
        float2 v0 = unpack2(acc[i][0]);
        float2 v1 = unpack2(acc[i][1]);
        float2 v2 = unpack2(acc[i][2]);
        float2 v3 = unpack2(acc[i][3]);
        float4 o0 = make_float4(v0.x + bb[0], v0.y + bb[1], v1.x + bb[2], v1.y + bb[3]);
        float4 o1 = make_float4(v2.x + bb[4], v2.y + bb[5], v3.x + bb[6], v3.y + bb[7]);
        *(float4*)&g_gx[off]     = o0;
        *(float4*)&g_gx[off + 4] = o1;
    }
}

// ---------------------------------------------------------------------------
// Persistent recurrence kernel. Block b owns 8 hidden cols [b*8, b*8+8)
// -> 32 gate cols. Wh slice (1024x32, 128KB) RESIDENT in smem for all 256
// steps. Per step: 64x32 tile of h @ Wh (K=1024), add gx, LSTM cell, one
// grid barrier. h staged replicated; inner loop = 2 LDS.128 + 4 FFMA2 per k.
// ---------------------------------------------------------------------------
#define HPAD 132                 // replicated h row length (128+4)
#define WHS_F   (1024 * 32)      // Whs floats
#define ASR_F   (2 * 32 * HPAD)  // double-buffered replicated h staging
#define GSM_W   40               // gsm row stride (16B aligned)
#define RECUR_SMEM_BYTES ((WHS_F + ASR_F + 64 * GSM_W + 64 * 8) * 4)

__global__ __launch_bounds__(256) void layer_recur_kernel(
    const float* __restrict__ Wh,   // [1024][4096] this layer
    float* __restrict__ outp, int is_last)
{
    extern __shared__ float smem[];
    float* Whs = smem;                      // [1024][32]
    float* Asr = smem + WHS_F;              // [2][32][HPAD] replicated
    float* gsm = Asr + ASR_F;               // [64][GSM_W]
    float* csm = gsm + 64 * GSM_W;          // [64][8]

    const int tid = threadIdx.x;
    const int bk  = blockIdx.x;
    const int j0  = bk * 8;

    float* dst = is_last ? outp : (float*)g_hseq;

    // ---- load resident Wh slice: Whs[k][c], c = chunk*8 + cj <-> global col
    //      chunk*1024 + j0 + cj
    for (int k0 = 0; k0 < 1024; k0 += 32) {
        int k = k0 + (tid >> 3);
        int q = tid & 7;                       // q*4 local col = (q>>1)*8+(q&1)*4
        int gcol = (q >> 1) * 1024 + j0 + (q & 1) * 4;
        *(float4*)&Whs[k * 32 + q * 4] = *(const float4*)(Wh + (size_t)k * GG + gcol);
    }

    // ---- zero own h columns (buffer 0) and cell state
    {
        int r = tid >> 2;
        int c = (tid & 3) * 2;
        g_hbuf[0][r][j0 + c]     = 0.0f;
        g_hbuf[0][r][j0 + c + 1] = 0.0f;
        csm[r * 8 + c]     = 0.0f;
        csm[r * 8 + c + 1] = 0.0f;
    }
    grid_sync();

    // compute mapping: rg = row-group (rows 2rg,2rg+1), cg = col-group (cols cg*4..+3)
    const int rg = tid >> 3;              // 0..31
    const int cg = tid & 7;               // 0..7
    const int gxcol = (cg >> 1) * 1024 + j0 + (cg & 1) * 4;  // global gate col of c0

    // h staging mapping
    const int hrow = tid >> 2;            // 0..63
    const int hk   = (tid & 3) * 4;       // 0,4,8,12 (+16 second half)

    // cell mapping
    const int er = tid >> 2;              // 0..63
    const int ec = (tid & 3) * 2;         // 0,2,4,6

    for (int t = 0; t < TT; ++t) {
        // gx loads issued early (latency hidden under k-loop)
        size_t gb = ((size_t)t * BB + 2 * rg) * GG + gxcol;
        float4 gx0 = *(const float4*)&g_gx[gb];
        float4 gx1 = *(const float4*)&g_gx[gb + GG];

        ull a00 = 0ull, a01 = 0ull, a10 = 0ull, a11 = 0ull;

        if (t > 0) {
            const float* h = &g_hbuf[t & 1][0][0] + (size_t)hrow * HH;
            float4 h0 = *(const float4*)(h + hk);
            float4 h1 = *(const float4*)(h + 16 + hk);

            for (int c = 0; c < 32; ++c) {
                float* buf = Asr + (c & 1) * (32 * HPAD);
                // stage replicated h chunk
                *(float2*)&buf[(hk + 0) * HPAD + 2 * hrow]  = make_float2(h0.x, h0.x);
                *(float2*)&buf[(hk + 1) * HPAD + 2 * hrow]  = make_float2(h0.y, h0.y);
                *(float2*)&buf[(hk + 2) * HPAD + 2 * hrow]  = make_float2(h0.z, h0.z);
                *(float2*)&buf[(hk + 3) * HPAD + 2 * hrow]  = make_float2(h0.w, h0.w);
                *(float2*)&buf[(hk + 16) * HPAD + 2 * hrow] = make_float2(h1.x, h1.x);
                *(float2*)&buf[(hk + 17) * HPAD + 2 * hrow] = make_float2(h1.y, h1.y);
                *(float2*)&buf[(hk + 18) * HPAD + 2 * hrow] = make_float2(h1.z, h1.z);
                *(float2*)&buf[(hk + 19) * HPAD + 2 * hrow] = make_float2(h1.w, h1.w);
                __syncthreads();

                if (c < 31) {
                    const float* hn = h + (c + 1) * 32;
                    h0 = *(const float4*)(hn + hk);
                    h1 = *(const float4*)(hn + 16 + hk);
                }

                const float* wk = Whs + c * 32 * 32;
#pragma unroll
                for (int k = 0; k < 32; ++k) {
                    ulonglong2 a = *(const ulonglong2*)&buf[k * HPAD + 4 * rg];
                    ulonglong2 w = *(const ulonglong2*)&wk[k * 32 + cg * 4];
                    ffma2(a00, a.x, w.x); ffma2(a01, a.x, w.y);
                    ffma2(a10, a.y, w.x); ffma2(a11, a.y, w.y);
                }
                __syncthreads();
            }
        }

        // gates = gx + h@Wh -> gsm
        {
            float* g0 = &gsm[(2 * rg) * GSM_W + cg * 4];
            float* g1 = g0 + GSM_W;
            float2 v;
            v = unpack2(a00); g0[0] = gx0.x + v.x; g0[1] = gx0.y + v.y;
            v = unpack2(a01); g0[2] = gx0.z + v.x; g0[3] = gx0.w + v.y;
            v = unpack2(a10); g1[0] = gx1.x + v.x; g1[1] = gx1.y + v.y;
            v = unpack2(a11); g1[2] = gx1.z + v.x; g1[3] = gx1.w + v.y;
        }
        __syncthreads();

        // LSTM cell (block-local)
#pragma unroll
        for (int i = 0; i < 2; ++i) {
            int cc = ec + i;
            float zi = gsm[er * GSM_W + cc];
            float zf = gsm[er * GSM_W + 8 + cc];
            float zg = gsm[er * GSM_W + 16 + cc];
            float zo = gsm[er * GSM_W + 24 + cc];
            float ig = 1.0f / (1.0f + expf(-zi));
            float fg = 1.0f / (1.0f + expf(-zf));
            float og = 1.0f / (1.0f + expf(-zo));
            float gg = tanhf(zg);
            float cv = fg * csm[er * 8 + cc] + ig * gg;
            float hv = og * tanhf(cv);
            csm[er * 8 + cc] = cv;
            g_hbuf[(t + 1) & 1][er][j0 + cc] = hv;
            dst[(size_t)t * (BB * HH) + (size_t)er * HH + j0 + cc] = hv;
        }

        grid_sync();   // h(t) published before step t+1
    }
}

// ---------------------------------------------------------------------------
// Host launcher: 8 graph nodes (4 big GEMMs + 4 persistent layer kernels)
// ---------------------------------------------------------------------------
extern "C" void kernel_launch(void* const* d_in, const int* in_sizes, int n_in,
                              void* d_out, int out_size)
{
    const float* x    = (const float*)d_in[0];
    const float* Wx   = (const float*)d_in[1];
    const float* Wh   = (const float*)d_in[2];
    const float* bias = (const float*)d_in[3];
    float* out = (float*)d_out;

    cudaFuncSetAttribute(layer_recur_kernel,
                         cudaFuncAttributeMaxDynamicSharedMemorySize,
                         RECUR_SMEM_BYTES);

    dim3 gemm_grid(GG / 128, (TT * BB) / 128);   // (32, 128)

    for (int l = 0; l < LL; ++l) {
        long sT = (l == 0) ? (long)DD : (long)BB * HH;
        long sB = (l == 0) ? (long)TT * DD : (long)HH;

        gemm_in_kernel<<<gemm_grid, 256>>>(
            x, sT, sB,
            Wx + (size_t)l * DD * GG,
            bias + (size_t)l * GG,
            (l == 0) ? 0 : 1);

        layer_recur_kernel<<<NBLK, 256, RECUR_SMEM_BYTES>>>(
            Wh + (size_t)l * HH * GG,
            out,
            (l == LL - 1) ? 1 : 0);
    }
}

// round 6
// speedup vs baseline: 4.3379x; 4.3379x over previous
#include <cuda_runtime.h>
#include <cuda_bf16.h>
#include <math.h>
#include <stdint.h>

// Problem constants
#define BB 64      // batch
#define TT 256     // time steps
#define DD 1024    // input dim
#define HH 1024    // hidden dim
#define LL 4       // layers
#define GG 4096    // 4*H gate width
#define MM (TT*BB) // 16384 rows of the big GEMM
#define NBLK 128   // persistent grid size for recurrence

// ---------------------------------------------------------------------------
// Scratch (static device globals; no runtime allocation allowed)
// ---------------------------------------------------------------------------
__device__ float g_gx[(size_t)MM * GG];              // [T*B, 4H] gate pre-activations
__device__ __nv_bfloat16 g_ahi[(size_t)MM * DD];     // activations hi, [m][k]
__device__ __nv_bfloat16 g_alo[(size_t)MM * DD];     // activations lo
__device__ __nv_bfloat16 g_wthi[(size_t)GG * DD];    // Wx^T hi, [n][k]
__device__ __nv_bfloat16 g_wtlo[(size_t)GG * DD];    // Wx^T lo
__device__ __nv_bfloat16 g_whthi[(size_t)GG * HH];   // Wh^T hi, [n][k]
__device__ __nv_bfloat16 g_whtlo[(size_t)GG * HH];   // Wh^T lo
__device__ __nv_bfloat16 g_hbhi[2][BB][HH];          // h double buffer, hi
__device__ __nv_bfloat16 g_hblo[2][BB][HH];          // h double buffer, lo
__device__ unsigned g_bar_count;                     // grid barrier (zero-init)
__device__ volatile unsigned g_bar_gen;

// ---------------------------------------------------------------------------
// Helpers
// ---------------------------------------------------------------------------
__device__ __forceinline__ void bsplit(float v, __nv_bfloat16& hi, __nv_bfloat16& lo) {
    hi = __float2bfloat16(v);
    lo = __float2bfloat16(v - __bfloat162float(hi));
}
__device__ __forceinline__ uint32_t smem_u32(const void* p) {
    uint32_t a;
    asm("{ .reg .u64 t; cvta.to.shared.u64 t, %1; cvt.u32.u64 %0, t; }" : "=r"(a) : "l"(p));
    return a;
}
__device__ __forceinline__ void ldsm4(uint32_t* r, uint32_t addr) {
    asm volatile("ldmatrix.sync.aligned.m8n8.x4.shared.b16 {%0,%1,%2,%3}, [%4];"
                 : "=r"(r[0]), "=r"(r[1]), "=r"(r[2]), "=r"(r[3]) : "r"(addr));
}
__device__ __forceinline__ void mma_bf16(float* d, const uint32_t* a,
                                         uint32_t b0, uint32_t b1) {
    asm volatile(
        "mma.sync.aligned.m16n8k16.row.col.f32.bf16.bf16.f32 "
        "{%0,%1,%2,%3},{%4,%5,%6,%7},{%8,%9},{%0,%1,%2,%3};"
        : "+f"(d[0]), "+f"(d[1]), "+f"(d[2]), "+f"(d[3])
        : "r"(a[0]), "r"(a[1]), "r"(a[2]), "r"(a[3]), "r"(b0), "r"(b1));
}
#define CP16(d, s) asm volatile("cp.async.cg.shared.global [%0], [%1], 16;" \
                                :: "r"(d), "l"(s) : "memory")
#define CP_COMMIT() asm volatile("cp.async.commit_group;" ::: "memory")
#define CP_WAIT1()  asm volatile("cp.async.wait_group 1;" ::: "memory")
#define CP_WAIT0()  asm volatile("cp.async.wait_group 0;" ::: "memory")

// ---------------------------------------------------------------------------
// Software grid barrier (all NBLK blocks co-resident)
// ---------------------------------------------------------------------------
__device__ __forceinline__ void grid_sync() {
    __syncthreads();
    if (threadIdx.x == 0) {
        __threadfence();
        unsigned gen = g_bar_gen;
        if (atomicAdd(&g_bar_count, 1u) == NBLK - 1) {
            g_bar_count = 0;
            __threadfence();
            g_bar_gen = gen + 1;
        } else {
            while (g_bar_gen == gen) { }
            __threadfence();
        }
    }
    __syncthreads();
}

// ---------------------------------------------------------------------------
// prep_x: x [B,T,D] fp32 -> g_ahi/g_alo [m=t*B+b][k] bf16 hi/lo
// ---------------------------------------------------------------------------
__global__ __launch_bounds__(256) void prep_x_kernel(const float* __restrict__ x) {
    size_t id = (size_t)blockIdx.x * 256 + threadIdx.x;   // float4 index
    int m = (int)(id >> 8);
    int d = (int)(id & 255) * 4;
    int b = m & (BB - 1), t = m >> 6;
    float4 v = *(const float4*)(x + ((size_t)b * TT + t) * DD + d);
    __nv_bfloat16 h0, h1, h2, h3, l0, l1, l2, l3;
    bsplit(v.x, h0, l0); bsplit(v.y, h1, l1);
    bsplit(v.z, h2, l2); bsplit(v.w, h3, l3);
    size_t o = (size_t)m * DD + d;
    *(__nv_bfloat162*)&g_ahi[o]     = __nv_bfloat162(h0, h1);
    *(__nv_bfloat162*)&g_ahi[o + 2] = __nv_bfloat162(h2, h3);
    *(__nv_bfloat162*)&g_alo[o]     = __nv_bfloat162(l0, l1);
    *(__nv_bfloat162*)&g_alo[o + 2] = __nv_bfloat162(l2, l3);
}

// ---------------------------------------------------------------------------
// prep_wt: W [1024 k][4096 n] fp32 -> W^T hi/lo [n][k] bf16 (transpose+split)
// sel=0 -> g_wthi/g_wtlo (Wx), sel=1 -> g_whthi/g_whtlo (Wh)
// ---------------------------------------------------------------------------
__global__ __launch_bounds__(256) void prep_wt_kernel(const float* __restrict__ W,
                                                      int sel) {
    __shared__ float tile[32][33];
    __nv_bfloat16* hi = sel ? g_whthi : g_wthi;
    __nv_bfloat16* lo = sel ? g_whtlo : g_wtlo;
    int n0 = blockIdx.x * 32, k0 = blockIdx.y * 32;
    int ty = threadIdx.x >> 5, tx = threadIdx.x & 31;
#pragma unroll
    for (int i = 0; i < 4; ++i) {
        int kk = ty + i * 8;
        tile[kk][tx] = W[(size_t)(k0 + kk) * GG + n0 + tx];
    }
    __syncthreads();
#pragma unroll
    for (int i = 0; i < 4; ++i) {
        int a = ty + i * 8;                 // local n
        float v = tile[tx][a];
        __nv_bfloat16 h, l; bsplit(v, h, l);
        size_t o = (size_t)(n0 + a) * DD + k0 + tx;
        hi[o] = h;
        lo[o] = l;
    }
}

// ---------------------------------------------------------------------------
// Tensor-core input GEMM via mma.sync (HMMA):
//   g_gx[m][n] = sum_k A[m][k]*W[k][n] + bias[n], 3-term bf16 split.
// Block tile 128x128, 8 warps x (32x64), k-chunks of 64, cp.async pipelined.
// smem rows padded to 72 halves (144B) -> conflict-free ldmatrix.
// ---------------------------------------------------------------------------
#define G_ARR  (128 * 72)           // halves per array
#define G_BUFH (4 * G_ARR)          // halves per buffer (Ahi,Alo,Bhi,Blo)
#define G_SMEM (2 * G_BUFH * 2)     // bytes (double buffered) = 147456

__global__ __launch_bounds__(256) void gemm_tc_kernel(const float* __restrict__ bias) {
    extern __shared__ char sm[];
    uint32_t sbase = smem_u32(sm);
    const int tid = threadIdx.x, lane = tid & 31, wid = tid >> 5;
    const int wm = wid >> 1, wn = wid & 1;
    const int m0 = blockIdx.y * 128, n0 = blockIdx.x * 128;

    float acc[2][8][4];
#pragma unroll
    for (int f = 0; f < 2; ++f)
#pragma unroll
        for (int q = 0; q < 8; ++q)
#pragma unroll
            for (int e = 0; e < 4; ++e) acc[f][q][e] = 0.0f;

    const uint32_t lrow = lane & 15, lcolq = (lane >> 4) * 8;

#define G_STAGE(kc) do {                                                      \
    uint32_t dstb = sbase + ((kc) & 1) * (G_BUFH * 2);                        \
    _Pragma("unroll")                                                         \
    for (int i = 0; i < 4; ++i) {                                             \
        int idx = tid + i * 256;                                              \
        int row = idx >> 3, q = idx & 7;                                      \
        size_t ga = (size_t)(m0 + row) * DD + (kc) * 64 + q * 8;              \
        size_t gb = (size_t)(n0 + row) * DD + (kc) * 64 + q * 8;              \
        uint32_t off = (uint32_t)(row * 72 + q * 8) * 2;                      \
        CP16(dstb + 0 * (G_ARR * 2) + off, g_ahi + ga);                       \
        CP16(dstb + 1 * (G_ARR * 2) + off, g_alo + ga);                       \
        CP16(dstb + 2 * (G_ARR * 2) + off, g_wthi + gb);                      \
        CP16(dstb + 3 * (G_ARR * 2) + off, g_wtlo + gb);                      \
    }                                                                         \
} while (0)

    G_STAGE(0); CP_COMMIT();

    for (int kc = 0; kc < 16; ++kc) {
        if (kc < 15) { G_STAGE(kc + 1); CP_COMMIT(); CP_WAIT1(); }
        else         { CP_WAIT0(); }
        __syncthreads();

        uint32_t bufb = sbase + (kc & 1) * (G_BUFH * 2);
#pragma unroll
        for (int s = 0; s < 4; ++s) {
            uint32_t koff = (s * 16 + lcolq) * 2;
            uint32_t ahi[2][4], alo[2][4];
#pragma unroll
            for (int f = 0; f < 2; ++f) {
                uint32_t a = bufb + (uint32_t)((wm * 32 + f * 16 + lrow) * 72) * 2 + koff;
                ldsm4(ahi[f], a);
                ldsm4(alo[f], a + G_ARR * 2);
            }
#pragma unroll
            for (int q = 0; q < 4; ++q) {
                uint32_t b = bufb + 2 * (G_ARR * 2)
                           + (uint32_t)((wn * 64 + q * 16 + lrow) * 72) * 2 + koff;
                uint32_t bh[4], bl[4];
                ldsm4(bh, b);
                ldsm4(bl, b + G_ARR * 2);
#pragma unroll
                for (int f = 0; f < 2; ++f) {
                    mma_bf16(acc[f][2 * q],     ahi[f], bh[0], bh[2]);
                    mma_bf16(acc[f][2 * q + 1], ahi[f], bh[1], bh[3]);
                    mma_bf16(acc[f][2 * q],     ahi[f], bl[0], bl[2]);
                    mma_bf16(acc[f][2 * q + 1], ahi[f], bl[1], bl[3]);
                    mma_bf16(acc[f][2 * q],     alo[f], bh[0], bh[2]);
                    mma_bf16(acc[f][2 * q + 1], alo[f], bh[1], bh[3]);
                }
            }
        }
        __syncthreads();
    }

    // epilogue: bias add + store
#pragma unroll
    for (int f = 0; f < 2; ++f) {
        int row = m0 + wm * 32 + f * 16 + (lane >> 2);
#pragma unroll
        for (int q = 0; q < 8; ++q) {
            int col = n0 + wn * 64 + q * 8 + (lane & 3) * 2;
            float2 bv = *(const float2*)&bias[col];
            *(float2*)&g_gx[(size_t)row * GG + col] =
                make_float2(acc[f][q][0] + bv.x, acc[f][q][1] + bv.y);
            *(float2*)&g_gx[(size_t)(row + 8) * GG + col] =
                make_float2(acc[f][q][2] + bv.x, acc[f][q][3] + bv.y);
        }
    }
#undef G_STAGE
}

// ---------------------------------------------------------------------------
// Persistent tensor-core recurrence. Block b owns 8 hidden cols (j0h=b*8)
// -> 32 gate cols (local col = chunk*8+cj <-> global chunk*1024+j0h+cj).
// Per step: gates[64x32] = h[64x1024] @ WhT^T (3-term bf16 HMMA), k-chunks of
// 64, warp tile 32x16 with k-parity split (8 warps = 2m x 2n x 2kh),
// partial-sum reduction in smem, block-local LSTM cell, one grid barrier.
// ---------------------------------------------------------------------------
#define R_AHI 0
#define R_ALO (64 * 72)
#define R_BHI (2 * 64 * 72)
#define R_BLO (2 * 64 * 72 + 32 * 72)
#define R_BUFH (2 * 64 * 72 + 2 * 32 * 72)     // 13824 halves per buffer
#define R_PART_OFF (2 * R_BUFH * 2)            // 55296 bytes
#define R_CSM_OFF  (R_PART_OFF + 2 * 64 * 36 * 4)   // +18432 = 73728
#define R_SMEM     (R_CSM_OFF + 64 * 8 * 4)         // 75776 bytes

__global__ __launch_bounds__(256) void layer_recur_kernel(
    float* __restrict__ outp, int is_last)
{
    extern __shared__ char sm[];
    float* part = (float*)(sm + R_PART_OFF);    // [2][64][36]
    float* csm  = (float*)(sm + R_CSM_OFF);     // [64][8]
    uint32_t sbase = smem_u32(sm);

    const int tid = threadIdx.x, lane = tid & 31, wid = tid >> 5;
    const int wm = (wid >> 2) & 1, wn = (wid >> 1) & 1, kh = wid & 1;
    const int j0h = blockIdx.x * 8;

    const uint32_t lrow = lane & 15, lcolq = (lane >> 4) * 8;
    const int er = tid >> 2, ec = (tid & 3) * 2;

    // zero cell state
    csm[er * 8 + ec]     = 0.0f;
    csm[er * 8 + ec + 1] = 0.0f;
    __syncthreads();

    for (int t = 0; t < TT; ++t) {
        // prefetch input-side gates
        float2 gxv[4];
        {
            size_t base = ((size_t)t * BB + er) * GG + j0h + ec;
#pragma unroll
            for (int c = 0; c < 4; ++c)
                gxv[c] = *(const float2*)&g_gx[base + (size_t)c * 1024];
        }

        float acc[2][2][4];
#pragma unroll
        for (int f = 0; f < 2; ++f)
#pragma unroll
            for (int n = 0; n < 2; ++n)
#pragma unroll
                for (int e = 0; e < 4; ++e) acc[f][n][e] = 0.0f;

        if (t > 0) {
            const __nv_bfloat16* hhi = &g_hbhi[t & 1][0][0];
            const __nv_bfloat16* hlo = &g_hblo[t & 1][0][0];

#define R_STAGE(kc) do {                                                      \
    uint32_t dstb = sbase + ((kc) & 1) * (R_BUFH * 2);                        \
    _Pragma("unroll")                                                         \
    for (int i = 0; i < 2; ++i) {                                             \
        int idx = tid + i * 256;                                              \
        int row = idx >> 3, q = idx & 7;                                      \
        size_t gs = (size_t)row * HH + (kc) * 64 + q * 8;                     \
        uint32_t off = (uint32_t)(row * 72 + q * 8) * 2;                      \
        CP16(dstb + R_AHI * 2 + off, hhi + gs);                               \
        CP16(dstb + R_ALO * 2 + off, hlo + gs);                               \
    }                                                                         \
    {                                                                         \
        int row = tid >> 3, q = tid & 7;                                      \
        int gc = (row >> 3) * 1024 + j0h + (row & 7);                         \
        size_t gs = (size_t)gc * HH + (kc) * 64 + q * 8;                      \
        uint32_t off = (uint32_t)(row * 72 + q * 8) * 2;                      \
        CP16(dstb + R_BHI * 2 + off, g_whthi + gs);                           \
        CP16(dstb + R_BLO * 2 + off, g_whtlo + gs);                           \
    }                                                                         \
} while (0)

            R_STAGE(0); CP_COMMIT();

            for (int kc = 0; kc < 16; ++kc) {
                if (kc < 15) { R_STAGE(kc + 1); CP_COMMIT(); CP_WAIT1(); }
                else         { CP_WAIT0(); }
                __syncthreads();

                uint32_t bufb = sbase + (kc & 1) * (R_BUFH * 2);
#pragma unroll
                for (int si = 0; si < 2; ++si) {
                    int s = kh + si * 2;
                    uint32_t koff = (uint32_t)(s * 16 + lcolq) * 2;
                    uint32_t a0 = bufb + (uint32_t)((wm * 32 + lrow) * 72) * 2 + koff;
                    uint32_t a1 = a0 + (uint32_t)(16 * 72) * 2;
                    uint32_t ahi0[4], ahi1[4], alo0[4], alo1[4];
                    ldsm4(ahi0, a0);
                    ldsm4(ahi1, a1);
                    ldsm4(alo0, a0 + (R_ALO - R_AHI) * 2);
                    ldsm4(alo1, a1 + (R_ALO - R_AHI) * 2);
                    uint32_t bb = bufb + R_BHI * 2
                                + (uint32_t)((wn * 16 + lrow) * 72) * 2 + koff;
                    uint32_t bh[4], bl[4];
                    ldsm4(bh, bb);
                    ldsm4(bl, bb + (R_BLO - R_BHI) * 2);

                    mma_bf16(acc[0][0], ahi0, bh[0], bh[2]);
                    mma_bf16(acc[0][1], ahi0, bh[1], bh[3]);
                    mma_bf16(acc[1][0], ahi1, bh[0], bh[2]);
                    mma_bf16(acc[1][1], ahi1, bh[1], bh[3]);
                    mma_bf16(acc[0][0], ahi0, bl[0], bl[2]);
                    mma_bf16(acc[0][1], ahi0, bl[1], bl[3]);
                    mma_bf16(acc[1][0], ahi1, bl[0], bl[2]);
                    mma_bf16(acc[1][1], ahi1, bl[1], bl[3]);
                    mma_bf16(acc[0][0], alo0, bh[0], bh[2]);
                    mma_bf16(acc[0][1], alo0, bh[1], bh[3]);
                    mma_bf16(acc[1][0], alo1, bh[0], bh[2]);
                    mma_bf16(acc[1][1], alo1, bh[1], bh[3]);
                }
                __syncthreads();
            }
#undef R_STAGE
        }

        // store partial sums: part[kh][row][col]
        {
            int prow = wm * 32 + (lane >> 2);
            int pcol = wn * 16 + (lane & 3) * 2;
            float* pb = part + kh * (64 * 36);
#pragma unroll
            for (int f = 0; f < 2; ++f)
#pragma unroll
                for (int nt = 0; nt < 2; ++nt) {
                    float* p = pb + (size_t)(prow + f * 16) * 36 + pcol + nt * 8;
                    p[0] = acc[f][nt][0];
                    p[1] = acc[f][nt][1];
                    p[8 * 36]     = acc[f][nt][2];
                    p[8 * 36 + 1] = acc[f][nt][3];
                }
        }
        __syncthreads();

        // LSTM cell (block-local); gate order i,f,g,o by chunk
        int nb = (t + 1) & 1;
#pragma unroll
        for (int i = 0; i < 2; ++i) {
            int cc = ec + i;
            float z[4];
#pragma unroll
            for (int c = 0; c < 4; ++c) {
                int lc = c * 8 + cc;
                z[c] = part[er * 36 + lc] + part[64 * 36 + er * 36 + lc]
                     + ((const float*)&gxv[c])[i];
            }
            float ig = 1.0f / (1.0f + expf(-z[0]));
            float fg = 1.0f / (1.0f + expf(-z[1]));
            float gg = tanhf(z[2]);
            float og = 1.0f / (1.0f + expf(-z[3]));
            float cv = fg * csm[er * 8 + cc] + ig * gg;
            float hv = og * tanhf(cv);
            csm[er * 8 + cc] = cv;
            __nv_bfloat16 hi, lo; bsplit(hv, hi, lo);
            g_hbhi[nb][er][j0h + cc] = hi;
            g_hblo[nb][er][j0h + cc] = lo;
            if (is_last) {
                outp[(size_t)t * (BB * HH) + (size_t)er * HH + j0h + cc] = hv;
            } else {
                size_t o = ((size_t)t * BB + er) * DD + j0h + cc;
                g_ahi[o] = hi;
                g_alo[o] = lo;
            }
        }

        grid_sync();   // publish h(t) before step t+1
    }
}

// ---------------------------------------------------------------------------
// Host launcher: 1 + 4*(2 preps + gemm + recur) = 17 graph nodes
// Inputs: x [B,T,D], Wx [L,D,4H], Wh [L,H,4H], b [L,4H]. Output [T,B,H] fp32.
// ---------------------------------------------------------------------------
extern "C" void kernel_launch(void* const* d_in, const int* in_sizes, int n_in,
                              void* d_out, int out_size)
{
    const float* x    = (const float*)d_in[0];
    const float* Wx   = (const float*)d_in[1];
    const float* Wh   = (const float*)d_in[2];
    const float* bias = (const float*)d_in[3];
    float* out = (float*)d_out;

    cudaFuncSetAttribute(gemm_tc_kernel,
                         cudaFuncAttributeMaxDynamicSharedMemorySize, G_SMEM);
    cudaFuncSetAttribute(layer_recur_kernel,
                         cudaFuncAttributeMaxDynamicSharedMemorySize, R_SMEM);

    prep_x_kernel<<<MM * DD / 4 / 256, 256>>>(x);

    for (int l = 0; l < LL; ++l) {
        prep_wt_kernel<<<dim3(GG / 32, DD / 32), 256>>>(Wx + (size_t)l * DD * GG, 0);
        prep_wt_kernel<<<dim3(GG / 32, HH / 32), 256>>>(Wh + (size_t)l * HH * GG, 1);

        gemm_tc_kernel<<<dim3(GG / 128, MM / 128), 256, G_SMEM>>>(
            bias + (size_t)l * GG);

        layer_recur_kernel<<<NBLK, 256, R_SMEM>>>(out, (l == LL - 1) ? 1 : 0);
    }
}

// round 8
// speedup vs baseline: 4.5767x; 1.0550x over previous
#include <cuda_runtime.h>
#include <cuda_bf16.h>
#include <math.h>
#include <stdint.h>

// Problem constants
#define BB 64      // batch
#define TT 256     // time steps
#define DD 1024    // input dim
#define HH 1024    // hidden dim
#define LL 4       // layers
#define GG 4096    // 4*H gate width
#define MM (TT*BB) // 16384 rows of the big GEMM
#define NBLK 128   // persistent grid size for recurrence

// ---------------------------------------------------------------------------
// Scratch (static device globals; no runtime allocation allowed)
// ---------------------------------------------------------------------------
__device__ float g_gx[(size_t)MM * GG];              // [T*B, 4H] gate pre-activations
__device__ __nv_bfloat16 g_ahi[(size_t)MM * DD];     // activations hi, [m][k]
__device__ __nv_bfloat16 g_alo[(size_t)MM * DD];     // activations lo
__device__ __nv_bfloat16 g_wthi[(size_t)GG * DD];    // Wx^T hi, [n][k]
__device__ __nv_bfloat16 g_wtlo[(size_t)GG * DD];    // Wx^T lo
__device__ __nv_bfloat16 g_whthi[(size_t)GG * HH];   // Wh^T hi, [n][k]
__device__ __nv_bfloat16 g_whtlo[(size_t)GG * HH];   // Wh^T lo
__device__ __nv_bfloat16 g_hbhi[2][BB][HH];          // h double buffer, hi
__device__ __nv_bfloat16 g_hblo[2][BB][HH];          // h double buffer, lo
__device__ unsigned g_bar_count;                     // grid barrier (zero-init)
__device__ volatile unsigned g_bar_gen;

// ---------------------------------------------------------------------------
// Helpers
// ---------------------------------------------------------------------------
__device__ __forceinline__ void bsplit(float v, __nv_bfloat16& hi, __nv_bfloat16& lo) {
    hi = __float2bfloat16(v);
    lo = __float2bfloat16(v - __bfloat162float(hi));
}
__device__ __forceinline__ uint32_t smem_u32(const void* p) {
    uint32_t a;
    asm("{ .reg .u64 t; cvta.to.shared.u64 t, %1; cvt.u32.u64 %0, t; }" : "=r"(a) : "l"(p));
    return a;
}
__device__ __forceinline__ void ldsm4(uint32_t* r, uint32_t addr) {
    asm volatile("ldmatrix.sync.aligned.m8n8.x4.shared.b16 {%0,%1,%2,%3}, [%4];"
                 : "=r"(r[0]), "=r"(r[1]), "=r"(r[2]), "=r"(r[3]) : "r"(addr));
}
__device__ __forceinline__ void mma_bf16(float* d, const uint32_t* a,
                                         uint32_t b0, uint32_t b1) {
    asm volatile(
        "mma.sync.aligned.m16n8k16.row.col.f32.bf16.bf16.f32 "
        "{%0,%1,%2,%3},{%4,%5,%6,%7},{%8,%9},{%0,%1,%2,%3};"
        : "+f"(d[0]), "+f"(d[1]), "+f"(d[2]), "+f"(d[3])
        : "r"(a[0]), "r"(a[1]), "r"(a[2]), "r"(a[3]), "r"(b0), "r"(b1));
}
#define CP16(d, s) asm volatile("cp.async.cg.shared.global [%0], [%1], 16;" \
                                :: "r"(d), "l"(s) : "memory")
#define CP_COMMIT() asm volatile("cp.async.commit_group;" ::: "memory")
#define CP_WAIT1()  asm volatile("cp.async.wait_group 1;" ::: "memory")
#define CP_WAIT0()  asm volatile("cp.async.wait_group 0;" ::: "memory")

// ---------------------------------------------------------------------------
// Software grid barrier (all NBLK blocks co-resident)
// ---------------------------------------------------------------------------
__device__ __forceinline__ void grid_sync() {
    __syncthreads();
    if (threadIdx.x == 0) {
        __threadfence();
        unsigned gen = g_bar_gen;
        if (atomicAdd(&g_bar_count, 1u) == NBLK - 1) {
            g_bar_count = 0;
            __threadfence();
            g_bar_gen = gen + 1;
        } else {
            while (g_bar_gen == gen) { }
            __threadfence();
        }
    }
    __syncthreads();
}

// ---------------------------------------------------------------------------
// prep_x: x [B,T,D] fp32 -> g_ahi/g_alo [m=t*B+b][k] bf16 hi/lo
// ---------------------------------------------------------------------------
__global__ __launch_bounds__(256) void prep_x_kernel(const float* __restrict__ x) {
    size_t id = (size_t)blockIdx.x * 256 + threadIdx.x;   // float4 index
    int m = (int)(id >> 8);
    int d = (int)(id & 255) * 4;
    int b = m & (BB - 1), t = m >> 6;
    float4 v = *(const float4*)(x + ((size_t)b * TT + t) * DD + d);
    __nv_bfloat16 h0, h1, h2, h3, l0, l1, l2, l3;
    bsplit(v.x, h0, l0); bsplit(v.y, h1, l1);
    bsplit(v.z, h2, l2); bsplit(v.w, h3, l3);
    size_t o = (size_t)m * DD + d;
    *(__nv_bfloat162*)&g_ahi[o]     = __nv_bfloat162(h0, h1);
    *(__nv_bfloat162*)&g_ahi[o + 2] = __nv_bfloat162(h2, h3);
    *(__nv_bfloat162*)&g_alo[o]     = __nv_bfloat162(l0, l1);
    *(__nv_bfloat162*)&g_alo[o + 2] = __nv_bfloat162(l2, l3);
}

// ---------------------------------------------------------------------------
// prep_wt: W [1024 k][4096 n] fp32 -> W^T hi/lo [n][k] bf16 (transpose+split)
// sel=0 -> g_wthi/g_wtlo (Wx), sel=1 -> g_whthi/g_whtlo (Wh)
// ---------------------------------------------------------------------------
__global__ __launch_bounds__(256) void prep_wt_kernel(const float* __restrict__ W,
                                                      int sel) {
    __shared__ float tile[32][33];
    __nv_bfloat16* hi = sel ? g_whthi : g_wthi;
    __nv_bfloat16* lo = sel ? g_whtlo : g_wtlo;
    int n0 = blockIdx.x * 32, k0 = blockIdx.y * 32;
    int ty = threadIdx.x >> 5, tx = threadIdx.x & 31;
#pragma unroll
    for (int i = 0; i < 4; ++i) {
        int kk = ty + i * 8;
        tile[kk][tx] = W[(size_t)(k0 + kk) * GG + n0 + tx];
    }
    __syncthreads();
#pragma unroll
    for (int i = 0; i < 4; ++i) {
        int a = ty + i * 8;                 // local n
        float v = tile[tx][a];
        __nv_bfloat16 h, l; bsplit(v, h, l);
        size_t o = (size_t)(n0 + a) * DD + k0 + tx;
        hi[o] = h;
        lo[o] = l;
    }
}

// ---------------------------------------------------------------------------
// Tensor-core input GEMM via mma.sync (HMMA), 3-term bf16 split.
// Block tile 128x128, 8 warps x (32x64), k-chunks of 64, cp.async pipelined.
// ---------------------------------------------------------------------------
#define G_ARR  (128 * 72)           // halves per array
#define G_BUFH (4 * G_ARR)          // halves per buffer (Ahi,Alo,Bhi,Blo)
#define G_SMEM (2 * G_BUFH * 2)     // bytes (double buffered) = 147456

__global__ __launch_bounds__(256) void gemm_tc_kernel(const float* __restrict__ bias) {
    extern __shared__ char sm[];
    uint32_t sbase = smem_u32(sm);
    const int tid = threadIdx.x, lane = tid & 31, wid = tid >> 5;
    const int wm = wid >> 1, wn = wid & 1;
    const int m0 = blockIdx.y * 128, n0 = blockIdx.x * 128;

    float acc[2][8][4];
#pragma unroll
    for (int f = 0; f < 2; ++f)
#pragma unroll
        for (int q = 0; q < 8; ++q)
#pragma unroll
            for (int e = 0; e < 4; ++e) acc[f][q][e] = 0.0f;

    const uint32_t lrow = lane & 15, lcolq = (lane >> 4) * 8;

#define G_STAGE(kc) do {                                                      \
    uint32_t dstb = sbase + ((kc) & 1) * (G_BUFH * 2);                        \
    _Pragma("unroll")                                                         \
    for (int i = 0; i < 4; ++i) {                                             \
        int idx = tid + i * 256;                                              \
        int row = idx >> 3, q = idx & 7;                                      \
        size_t ga = (size_t)(m0 + row) * DD + (kc) * 64 + q * 8;              \
        size_t gb = (size_t)(n0 + row) * DD + (kc) * 64 + q * 8;              \
        uint32_t off = (uint32_t)(row * 72 + q * 8) * 2;                      \
        CP16(dstb + 0 * (G_ARR * 2) + off, g_ahi + ga);                       \
        CP16(dstb + 1 * (G_ARR * 2) + off, g_alo + ga);                       \
        CP16(dstb + 2 * (G_ARR * 2) + off, g_wthi + gb);                      \
        CP16(dstb + 3 * (G_ARR * 2) + off, g_wtlo + gb);                      \
    }                                                                         \
} while (0)

    G_STAGE(0); CP_COMMIT();

    for (int kc = 0; kc < 16; ++kc) {
        if (kc < 15) { G_STAGE(kc + 1); CP_COMMIT(); CP_WAIT1(); }
        else         { CP_WAIT0(); }
        __syncthreads();

        uint32_t bufb = sbase + (kc & 1) * (G_BUFH * 2);
#pragma unroll
        for (int s = 0; s < 4; ++s) {
            uint32_t koff = (s * 16 + lcolq) * 2;
            uint32_t ahi[2][4], alo[2][4];
#pragma unroll
            for (int f = 0; f < 2; ++f) {
                uint32_t a = bufb + (uint32_t)((wm * 32 + f * 16 + lrow) * 72) * 2 + koff;
                ldsm4(ahi[f], a);
                ldsm4(alo[f], a + G_ARR * 2);
            }
#pragma unroll
            for (int q = 0; q < 4; ++q) {
                uint32_t b = bufb + 2 * (G_ARR * 2)
                           + (uint32_t)((wn * 64 + q * 16 + lrow) * 72) * 2 + koff;
                uint32_t bh[4], bl[4];
                ldsm4(bh, b);
                ldsm4(bl, b + G_ARR * 2);
#pragma unroll
                for (int f = 0; f < 2; ++f) {
                    mma_bf16(acc[f][2 * q],     ahi[f], bh[0], bh[2]);
                    mma_bf16(acc[f][2 * q + 1], ahi[f], bh[1], bh[3]);
                    mma_bf16(acc[f][2 * q],     ahi[f], bl[0], bl[2]);
                    mma_bf16(acc[f][2 * q + 1], ahi[f], bl[1], bl[3]);
                    mma_bf16(acc[f][2 * q],     alo[f], bh[0], bh[2]);
                    mma_bf16(acc[f][2 * q + 1], alo[f], bh[1], bh[3]);
                }
            }
        }
        __syncthreads();
    }

    // epilogue: bias add + store
#pragma unroll
    for (int f = 0; f < 2; ++f) {
        int row = m0 + wm * 32 + f * 16 + (lane >> 2);
#pragma unroll
        for (int q = 0; q < 8; ++q) {
            int col = n0 + wn * 64 + q * 8 + (lane & 3) * 2;
            float2 bv = *(const float2*)&bias[col];
            *(float2*)&g_gx[(size_t)row * GG + col] =
                make_float2(acc[f][q][0] + bv.x, acc[f][q][1] + bv.y);
            *(float2*)&g_gx[(size_t)(row + 8) * GG + col] =
                make_float2(acc[f][q][2] + bv.x, acc[f][q][3] + bv.y);
        }
    }
#undef G_STAGE
}

// ---------------------------------------------------------------------------
// Persistent tensor-core recurrence, 512 threads (16 warps = 2m x 2n x 4k).
// Block b owns 8 hidden cols (j0h=b*8) -> 32 gate cols. K-chunks of 128
// (8 chunks/step), double-buffered cp.async, partials [4][64][36] reduced in
// the cell epilogue (1 element/thread), one grid barrier per step.
// ---------------------------------------------------------------------------
#define R_ROW  136                          // halves per smem row (128+8)
#define R_AHI  0
#define R_ALO  (64 * R_ROW)
#define R_BHI  (128 * R_ROW)
#define R_BLO  (160 * R_ROW)
#define R_BUFH (192 * R_ROW)                // 26112 halves = 52224 B per buffer
#define R_PART_OFF (2 * R_BUFH * 2)         // 104448 B
#define R_CSM_OFF  (R_PART_OFF + 4 * 64 * 36 * 4)   // +36864 = 141312
#define R_SMEM     (R_CSM_OFF + 64 * 8 * 4)         // 143360 B

__global__ __launch_bounds__(512) void layer_recur_kernel(
    float* __restrict__ outp, int is_last)
{
    extern __shared__ char sm[];
    float* part = (float*)(sm + R_PART_OFF);    // [4][64][36]
    float* csm  = (float*)(sm + R_CSM_OFF);     // [64][8]
    uint32_t sbase = smem_u32(sm);

    const int tid = threadIdx.x, lane = tid & 31, wid = tid >> 5;
    const int kh = wid & 3, wn = (wid >> 2) & 1, wm = (wid >> 3) & 1;
    const int j0h = blockIdx.x * 8;

    const uint32_t lrow = lane & 15, lcolq = (lane >> 4) * 8;
    const int er = tid >> 3, ec = tid & 7;      // 1 gate element per thread

    // zero cell state (512 threads cover 64x8 exactly)
    csm[tid] = 0.0f;
    __syncthreads();

    for (int t = 0; t < TT; ++t) {
        // prefetch input-side gates (1 scalar per gate chunk per thread)
        float gxv[4];
        {
            size_t base = ((size_t)t * BB + er) * GG + j0h + ec;
#pragma unroll
            for (int c = 0; c < 4; ++c)
                gxv[c] = g_gx[base + (size_t)c * 1024];
        }

        float acc[2][2][4];
#pragma unroll
        for (int f = 0; f < 2; ++f)
#pragma unroll
            for (int n = 0; n < 2; ++n)
#pragma unroll
                for (int e = 0; e < 4; ++e) acc[f][n][e] = 0.0f;

        if (t > 0) {
            const __nv_bfloat16* hhi = &g_hbhi[t & 1][0][0];
            const __nv_bfloat16* hlo = &g_hblo[t & 1][0][0];

#define R_STAGE(kc) do {                                                      \
    uint32_t dstb = sbase + ((kc) & 1) * (R_BUFH * 2);                        \
    _Pragma("unroll")                                                         \
    for (int i = 0; i < 2; ++i) {                                             \
        int idx = tid + i * 512;                                              \
        int row = idx >> 4, q = idx & 15;                                     \
        size_t gs = (size_t)row * HH + (kc) * 128 + q * 8;                    \
        uint32_t off = (uint32_t)(row * R_ROW + q * 8) * 2;                   \
        CP16(dstb + R_AHI * 2 + off, hhi + gs);                               \
        CP16(dstb + R_ALO * 2 + off, hlo + gs);                               \
    }                                                                         \
    {                                                                         \
        int row = tid >> 4, q = tid & 15;                                     \
        int gc = (row >> 3) * 1024 + j0h + (row & 7);                         \
        size_t gs = (size_t)gc * HH + (kc) * 128 + q * 8;                     \
        uint32_t off = (uint32_t)(row * R_ROW + q * 8) * 2;                   \
        CP16(dstb + R_BHI * 2 + off, g_whthi + gs);                           \
        CP16(dstb + R_BLO * 2 + off, g_whtlo + gs);                           \
    }                                                                         \
} while (0)

            R_STAGE(0); CP_COMMIT();

            for (int kc = 0; kc < 8; ++kc) {
                if (kc < 7) { R_STAGE(kc + 1); CP_COMMIT(); CP_WAIT1(); }
                else        { CP_WAIT0(); }
                __syncthreads();

                uint32_t bufb = sbase + (kc & 1) * (R_BUFH * 2);
#pragma unroll
                for (int si = 0; si < 2; ++si) {
                    int s = kh + si * 4;
                    uint32_t koff = (uint32_t)(s * 16 + lcolq) * 2;
                    uint32_t a0 = bufb + (uint32_t)((wm * 32 + lrow) * R_ROW) * 2 + koff;
                    uint32_t a1 = a0 + (uint32_t)(16 * R_ROW) * 2;
                    uint32_t ahi0[4], ahi1[4], alo0[4], alo1[4];
                    ldsm4(ahi0, a0);
                    ldsm4(ahi1, a1);
                    ldsm4(alo0, a0 + (R_ALO - R_AHI) * 2);
                    ldsm4(alo1, a1 + (R_ALO - R_AHI) * 2);
                    uint32_t bb = bufb + R_BHI * 2
                                + (uint32_t)((wn * 16 + lrow) * R_ROW) * 2 + koff;
                    uint32_t bh[4], bl[4];
                    ldsm4(bh, bb);
                    ldsm4(bl, bb + (R_BLO - R_BHI) * 2);

                    mma_bf16(acc[0][0], ahi0, bh[0], bh[2]);
                    mma_bf16(acc[0][1], ahi0, bh[1], bh[3]);
                    mma_bf16(acc[1][0], ahi1, bh[0], bh[2]);
                    mma_bf16(acc[1][1], ahi1, bh[1], bh[3]);
                    mma_bf16(acc[0][0], ahi0, bl[0], bl[2]);
                    mma_bf16(acc[0][1], ahi0, bl[1], bl[3]);
                    mma_bf16(acc[1][0], ahi1, bl[0], bl[2]);
                    mma_bf16(acc[1][1], ahi1, bl[1], bl[3]);
                    mma_bf16(acc[0][0], alo0, bh[0], bh[2]);
                    mma_bf16(acc[0][1], alo0, bh[1], bh[3]);
                    mma_bf16(acc[1][0], alo1, bh[0], bh[2]);
                    mma_bf16(acc[1][1], alo1, bh[1], bh[3]);
                }
                __syncthreads();
            }
#undef R_STAGE
        }

        // store partial sums: part[kh][row][col]
        {
            int prow = wm * 32 + (lane >> 2);
            int pcol = wn * 16 + (lane & 3) * 2;
            float* pb = part + kh * (64 * 36);
#pragma unroll
            for (int f = 0; f < 2; ++f)
#pragma unroll
                for (int nt = 0; nt < 2; ++nt) {
                    float* p = pb + (size_t)(prow + f * 16) * 36 + pcol + nt * 8;
                    p[0] = acc[f][nt][0];
                    p[1] = acc[f][nt][1];
                    p[8 * 36]     = acc[f][nt][2];
                    p[8 * 36 + 1] = acc[f][nt][3];
                }
        }
        __syncthreads();

        // LSTM cell: 1 element/thread; gate order i,f,g,o by chunk
        int nb = (t + 1) & 1;
        {
            float z[4];
#pragma unroll
            for (int c = 0; c < 4; ++c) {
                int lc = c * 8 + ec;
                float s = gxv[c];
#pragma unroll
                for (int p = 0; p < 4; ++p)
                    s += part[p * (64 * 36) + er * 36 + lc];
                z[c] = s;
            }
            float ig = 1.0f / (1.0f + expf(-z[0]));
            float fg = 1.0f / (1.0f + expf(-z[1]));
            float gg = tanhf(z[2]);
            float og = 1.0f / (1.0f + expf(-z[3]));
            float cv = fg * csm[er * 8 + ec] + ig * gg;
            float hv = og * tanhf(cv);
            csm[er * 8 + ec] = cv;
            __nv_bfloat16 hi, lo; bsplit(hv, hi, lo);
            g_hbhi[nb][er][j0h + ec] = hi;
            g_hblo[nb][er][j0h + ec] = lo;
            if (is_last) {
                outp[(size_t)t * (BB * HH) + (size_t)er * HH + j0h + ec] = hv;
            } else {
                size_t o = ((size_t)t * BB + er) * DD + j0h + ec;
                g_ahi[o] = hi;
                g_alo[o] = lo;
            }
        }

        grid_sync();   // publish h(t) before step t+1
    }
}

// ---------------------------------------------------------------------------
// Host launcher: 1 + 4*(2 preps + gemm + recur) = 17 graph nodes
// Inputs: x [B,T,D], Wx [L,D,4H], Wh [L,H,4H], b [L,4H]. Output [T,B,H] fp32.
// ---------------------------------------------------------------------------
extern "C" void kernel_launch(void* const* d_in, const int* in_sizes, int n_in,
                              void* d_out, int out_size)
{
    const float* x    = (const float*)d_in[0];
    const float* Wx   = (const float*)d_in[1];
    const float* Wh   = (const float*)d_in[2];
    const float* bias = (const float*)d_in[3];
    float* out = (float*)d_out;

    cudaFuncSetAttribute(gemm_tc_kernel,
                         cudaFuncAttributeMaxDynamicSharedMemorySize, G_SMEM);
    cudaFuncSetAttribute(layer_recur_kernel,
                         cudaFuncAttributeMaxDynamicSharedMemorySize, R_SMEM);

    prep_x_kernel<<<MM * DD / 4 / 256, 256>>>(x);

    for (int l = 0; l < LL; ++l) {
        prep_wt_kernel<<<dim3(GG / 32, DD / 32), 256>>>(Wx + (size_t)l * DD * GG, 0);
        prep_wt_kernel<<<dim3(GG / 32, HH / 32), 256>>>(Wh + (size_t)l * HH * GG, 1);

        gemm_tc_kernel<<<dim3(GG / 128, MM / 128), 256, G_SMEM>>>(
            bias + (size_t)l * GG);

        layer_recur_kernel<<<NBLK, 512, R_SMEM>>>(out, (l == LL - 1) ? 1 : 0);
    }
}